// round 14
// baseline (speedup 1.0000x reference)
#include <cuda_runtime.h>
#include <mma.h>

using namespace nvcuda;

// ----------------------------------------------------------------------------
// GCN 5-layer inference, N=50000 nodes, E=800000 edges, 128->64->64->64->64->16
//
// Output layout (flattened tuple): [log_softmax N*16][e1 N*64][e2][e3][e4][e5 N*16]
//
// This round (vs R13 launch failure):
//   - __launch_bounds__(512, 1) on the tc GEMM: caps regs at 128/thread so
//     512 threads x regs fits the 64K regs/block limit (R13's rejection).
//   - Otherwise identical: tf32 3x-compensated wmma GEMM @ 512 threads,
//     scalar layer-5 GEMM, fused agg16+log_softmax, proven CSR + agg64.
// ----------------------------------------------------------------------------

constexpr int N_NODES = 50000;
constexpr int N_EDGES = 800000;
constexpr int SCAN_CHUNK = 1024;
constexpr int NB = (N_NODES + SCAN_CHUNK - 1) / SCAN_CHUNK;   // 49

// Scratch for the per-layer dense GEMM result (max N x 64 fp32 = 12.8 MB).
__device__ float g_xw[(size_t)N_NODES * 64];

// CSR scratch
__device__ int   g_deg[N_NODES];
__device__ int   g_off[N_NODES + 1];
__device__ int   g_bsum[NB];
__device__ int   g_ecol[N_EDGES];
__device__ float g_ew[N_EDGES];

// ----------------------------------------------------------------------------
// Tensor-core GEMM (COLS=64): g_xw[N x 64] = act(X)[N x K] @ W[K x 64]
// 128-row tile, 512 threads (16 warps). Warp w: rows (w/2)*16, cols (w&1)*32.
// tf32 wmma m16n16k8, 3xTF32 compensation: X=Xh+Xl, W=Wh+Wl,
// XW ~= XhWh + XhWl + XlWh  (~1e-7 elementwise rel err).
// ----------------------------------------------------------------------------
constexpr int SX_LD = 72;   // padded leading dim (multiple of 8)

template <int K, bool RELU>
__global__ void __launch_bounds__(512, 1)
gemm_tc64_kernel(const float* __restrict__ X, const float* __restrict__ W) {
    extern __shared__ float smem[];
    float* sx_h = smem;                        // [128][SX_LD]
    float* sx_l = sx_h + 128 * SX_LD;          // [128][SX_LD]
    float* sw_h = sx_l + 128 * SX_LD;          // [64][64]
    float* sw_l = sw_h + 64 * 64;              // [64][64]

    const int tid  = threadIdx.x;              // 512 threads
    const int w    = tid >> 5;                 // warp 0..15
    const int rt   = w >> 1;                   // row tile 0..7  -> rows rt*16
    const int ch   = (w & 1) * 32;             // col half: 0 or 32
    const int row0 = blockIdx.x * 128;

    wmma::fragment<wmma::accumulator, 16, 16, 8, float> acc[2];
    wmma::fill_fragment(acc[0], 0.f);
    wmma::fill_fragment(acc[1], 0.f);

    for (int kt = 0; kt < K; kt += 64) {
        if (kt) __syncthreads();

        // Stage X tile (128 x 64), relu fused, tf32 hi/lo split.
        for (int i = tid; i < 128 * 16; i += 512) {
            int r = i >> 4, q = i & 15;
            int gr = row0 + r;
            float4 v = make_float4(0.f, 0.f, 0.f, 0.f);
            if (gr < N_NODES)
                v = *(const float4*)(X + (size_t)gr * K + kt + q * 4);
            if (RELU) {
                v.x = fmaxf(v.x, 0.f); v.y = fmaxf(v.y, 0.f);
                v.z = fmaxf(v.z, 0.f); v.w = fmaxf(v.w, 0.f);
            }
            float4 h, l;
            h.x = wmma::__float_to_tf32(v.x); l.x = wmma::__float_to_tf32(v.x - h.x);
            h.y = wmma::__float_to_tf32(v.y); l.y = wmma::__float_to_tf32(v.y - h.y);
            h.z = wmma::__float_to_tf32(v.z); l.z = wmma::__float_to_tf32(v.z - h.z);
            h.w = wmma::__float_to_tf32(v.w); l.w = wmma::__float_to_tf32(v.w - h.w);
            *(float4*)&sx_h[r * SX_LD + q * 4] = h;
            *(float4*)&sx_l[r * SX_LD + q * 4] = l;
        }
        // Stage W tile (64 x 64), tf32 hi/lo split.
        for (int i = tid; i < 64 * 16; i += 512) {
            int k = i >> 4, q = i & 15;
            float4 v = *(const float4*)(W + (size_t)(kt + k) * 64 + q * 4);
            float4 h, l;
            h.x = wmma::__float_to_tf32(v.x); l.x = wmma::__float_to_tf32(v.x - h.x);
            h.y = wmma::__float_to_tf32(v.y); l.y = wmma::__float_to_tf32(v.y - h.y);
            h.z = wmma::__float_to_tf32(v.z); l.z = wmma::__float_to_tf32(v.z - h.z);
            h.w = wmma::__float_to_tf32(v.w); l.w = wmma::__float_to_tf32(v.w - h.w);
            *(float4*)&sw_h[k * 64 + q * 4] = h;
            *(float4*)&sw_l[k * 64 + q * 4] = l;
        }
        __syncthreads();

#pragma unroll
        for (int k = 0; k < 64; k += 8) {
            wmma::fragment<wmma::matrix_a, 16, 16, 8, wmma::precision::tf32, wmma::row_major> ah, al;
            wmma::load_matrix_sync(ah, &sx_h[(rt * 16) * SX_LD + k], SX_LD);
            wmma::load_matrix_sync(al, &sx_l[(rt * 16) * SX_LD + k], SX_LD);
#pragma unroll
            for (int c = 0; c < 2; c++) {
                wmma::fragment<wmma::matrix_b, 16, 16, 8, wmma::precision::tf32, wmma::row_major> bh, bl;
                wmma::load_matrix_sync(bh, &sw_h[k * 64 + ch + c * 16], 64);
                wmma::load_matrix_sync(bl, &sw_l[k * 64 + ch + c * 16], 64);
                wmma::mma_sync(acc[c], ah, bh, acc[c]);   // hi*hi
                wmma::mma_sync(acc[c], ah, bl, acc[c]);   // hi*lo
                wmma::mma_sync(acc[c], al, bh, acc[c]);   // lo*hi
            }
        }
    }

    int gw0 = row0 + rt * 16;
    if (gw0 < N_NODES) {   // tiles never partial: 50000 % 16 == 0
        wmma::store_matrix_sync(g_xw + (size_t)gw0 * 64 + ch,      acc[0], 64, wmma::mem_row_major);
        wmma::store_matrix_sync(g_xw + (size_t)gw0 * 64 + ch + 16, acc[1], 64, wmma::mem_row_major);
    }
}

constexpr int SMEM_TC64 = (2 * 128 * SX_LD + 2 * 64 * 64) * 4;   // 104 KB

// ----------------------------------------------------------------------------
// Scalar GEMM for layer 5 (COLS=16): proven R7 kernel.
// 64-row tile, 64 threads, thread tile 4x4.
// ----------------------------------------------------------------------------
template <int K, int COLS, bool RELU>
__global__ void gemm_kernel(const float* __restrict__ X, const float* __restrict__ W) {
    constexpr int TX = COLS / 4;
    constexpr int NT = TX * 16;

    __shared__ float sx[64][68];
    __shared__ float sw[64][COLS];

    const int tid  = threadIdx.x;
    const int tx   = tid % TX;
    const int ty   = tid / TX;
    const int row0 = blockIdx.x * 64;

    float4 acc[4];
#pragma unroll
    for (int r = 0; r < 4; r++) acc[r] = make_float4(0.f, 0.f, 0.f, 0.f);

    for (int kt = 0; kt < K; kt += 64) {
        if (kt) __syncthreads();
        for (int i = tid; i < 64 * 16; i += NT) {
            int r = i >> 4, q = i & 15;
            int gr = row0 + r;
            float4 v = make_float4(0.f, 0.f, 0.f, 0.f);
            if (gr < N_NODES)
                v = *(const float4*)(X + (size_t)gr * K + kt + q * 4);
            if (RELU) {
                v.x = fmaxf(v.x, 0.f); v.y = fmaxf(v.y, 0.f);
                v.z = fmaxf(v.z, 0.f); v.w = fmaxf(v.w, 0.f);
            }
            *(float4*)&sx[r][q * 4] = v;
        }
        for (int i = tid; i < 64 * (COLS / 4); i += NT) {
            int k = i / (COLS / 4), q = i % (COLS / 4);
            *(float4*)&sw[k][q * 4] = *(const float4*)(W + (size_t)(kt + k) * COLS + q * 4);
        }
        __syncthreads();

#pragma unroll
        for (int k = 0; k < 64; k += 4) {
            float4 b0 = *(const float4*)&sw[k + 0][tx * 4];
            float4 b1 = *(const float4*)&sw[k + 1][tx * 4];
            float4 b2 = *(const float4*)&sw[k + 2][tx * 4];
            float4 b3 = *(const float4*)&sw[k + 3][tx * 4];
#pragma unroll
            for (int r = 0; r < 4; r++) {
                float4 a = *(const float4*)&sx[ty * 4 + r][k];
                acc[r].x += a.x * b0.x; acc[r].y += a.x * b0.y;
                acc[r].z += a.x * b0.z; acc[r].w += a.x * b0.w;
                acc[r].x += a.y * b1.x; acc[r].y += a.y * b1.y;
                acc[r].z += a.y * b1.z; acc[r].w += a.y * b1.w;
                acc[r].x += a.z * b2.x; acc[r].y += a.z * b2.y;
                acc[r].z += a.z * b2.z; acc[r].w += a.z * b2.w;
                acc[r].x += a.w * b3.x; acc[r].y += a.w * b3.y;
                acc[r].z += a.w * b3.z; acc[r].w += a.w * b3.w;
            }
        }
    }

#pragma unroll
    for (int r = 0; r < 4; r++) {
        int gr = row0 + ty * 4 + r;
        if (gr < N_NODES)
            *(float4*)(g_xw + (size_t)gr * COLS + tx * 4) = acc[r];
    }
}

// ----------------------------------------------------------------------------
// CSR build (proven R7 version)
// ----------------------------------------------------------------------------
__global__ void zero_deg_kernel() {
    int i = blockIdx.x * blockDim.x + threadIdx.x;
    if (i < N_NODES) g_deg[i] = 0;
}

__global__ void hist_kernel(const int* __restrict__ erow) {
    int e = blockIdx.x * blockDim.x + threadIdx.x;
    if (e < N_EDGES) atomicAdd(&g_deg[__ldg(erow + e)], 1);
}

__global__ void scan1_kernel() {
    __shared__ int sh[256];
    int b = blockIdx.x, t = threadIdx.x;
    int base = b * SCAN_CHUNK + t * 4;
    int d0 = 0, d1 = 0, d2 = 0, d3 = 0;
    if (base + 0 < N_NODES) d0 = g_deg[base + 0];
    if (base + 1 < N_NODES) d1 = g_deg[base + 1];
    if (base + 2 < N_NODES) d2 = g_deg[base + 2];
    if (base + 3 < N_NODES) d3 = g_deg[base + 3];
    int s = d0 + d1 + d2 + d3;
    sh[t] = s;
    __syncthreads();
    for (int off = 1; off < 256; off <<= 1) {
        int v = (t >= off) ? sh[t - off] : 0;
        __syncthreads();
        sh[t] += v;
        __syncthreads();
    }
    int excl = sh[t] - s;
    if (t == 255) g_bsum[b] = sh[255];
    if (base + 0 < N_NODES) g_off[base + 0] = excl;
    if (base + 1 < N_NODES) g_off[base + 1] = excl + d0;
    if (base + 2 < N_NODES) g_off[base + 2] = excl + d0 + d1;
    if (base + 3 < N_NODES) g_off[base + 3] = excl + d0 + d1 + d2;
}

__global__ void scan2_kernel() {
    __shared__ int sh[64];
    int t = threadIdx.x;
    int v = (t < NB) ? g_bsum[t] : 0;
    sh[t] = v;
    __syncthreads();
    for (int off = 1; off < 64; off <<= 1) {
        int u = (t >= off) ? sh[t - off] : 0;
        __syncthreads();
        sh[t] += u;
        __syncthreads();
    }
    if (t < NB) g_bsum[t] = sh[t] - v;   // exclusive
}

__global__ void scan3_kernel() {
    int i = blockIdx.x * blockDim.x + threadIdx.x;
    if (i < N_NODES) {
        g_off[i] += g_bsum[i / SCAN_CHUNK];
        g_deg[i] = 0;
    }
    if (i == 0) g_off[N_NODES] = N_EDGES;
}

__global__ void fill_kernel(const int* __restrict__ erow, const int* __restrict__ ecol,
                            const float* __restrict__ ew) {
    int e = blockIdx.x * blockDim.x + threadIdx.x;
    if (e >= N_EDGES) return;
    int r = __ldg(erow + e);
    int pos = g_off[r] + atomicAdd(&g_deg[r], 1);
    g_ecol[pos] = __ldg(ecol + e);
    g_ew[pos]   = __ldg(ew + e);
}

// ----------------------------------------------------------------------------
// Per-row aggregation (64 features): dst[row] = b + sum w_e * g_xw[col_e]
// ----------------------------------------------------------------------------
__global__ void agg64_kernel(const float* __restrict__ bias, float* __restrict__ dst) {
    int t = blockIdx.x * blockDim.x + threadIdx.x;
    if (t >= N_NODES * 16) return;
    int row = t >> 4, q = t & 15;
    float4 acc = *(const float4*)(bias + q * 4);
    int i = __ldg(&g_off[row]), end = __ldg(&g_off[row + 1]);
    for (; i + 1 < end; i += 2) {
        int c0 = __ldg(&g_ecol[i]);     float w0 = __ldg(&g_ew[i]);
        int c1 = __ldg(&g_ecol[i + 1]); float w1 = __ldg(&g_ew[i + 1]);
        float4 v0 = *(const float4*)(g_xw + (size_t)c0 * 64 + q * 4);
        float4 v1 = *(const float4*)(g_xw + (size_t)c1 * 64 + q * 4);
        acc.x += w0 * v0.x + w1 * v1.x;
        acc.y += w0 * v0.y + w1 * v1.y;
        acc.z += w0 * v0.z + w1 * v1.z;
        acc.w += w0 * v0.w + w1 * v1.w;
    }
    if (i < end) {
        int c = __ldg(&g_ecol[i]); float w = __ldg(&g_ew[i]);
        float4 v = *(const float4*)(g_xw + (size_t)c * 64 + q * 4);
        acc.x += w * v.x; acc.y += w * v.y; acc.z += w * v.z; acc.w += w * v.w;
    }
    *(float4*)(dst + (size_t)row * 64 + q * 4) = acc;
}

// ----------------------------------------------------------------------------
// Layer-5 aggregation (16 features) with FUSED log_softmax.
// Quad of threads (q=0..3) owns a row; reduction via shfl_xor 1,2.
// ----------------------------------------------------------------------------
__global__ void agg16_lsm_kernel(const float* __restrict__ bias,
                                 float* __restrict__ e5, float* __restrict__ out) {
    int t = blockIdx.x * blockDim.x + threadIdx.x;
    bool valid = (t < N_NODES * 4);
    int tc = valid ? t : (N_NODES * 4 - 1);
    int row = tc >> 2, q = tc & 3;

    float4 acc = *(const float4*)(bias + q * 4);
    int i = __ldg(&g_off[row]), end = __ldg(&g_off[row + 1]);
    for (; i + 1 < end; i += 2) {
        int c0 = __ldg(&g_ecol[i]);     float w0 = __ldg(&g_ew[i]);
        int c1 = __ldg(&g_ecol[i + 1]); float w1 = __ldg(&g_ew[i + 1]);
        float4 v0 = *(const float4*)(g_xw + (size_t)c0 * 16 + q * 4);
        float4 v1 = *(const float4*)(g_xw + (size_t)c1 * 16 + q * 4);
        acc.x += w0 * v0.x + w1 * v1.x;
        acc.y += w0 * v0.y + w1 * v1.y;
        acc.z += w0 * v0.z + w1 * v1.z;
        acc.w += w0 * v0.w + w1 * v1.w;
    }
    if (i < end) {
        int c = __ldg(&g_ecol[i]); float w = __ldg(&g_ew[i]);
        float4 v = *(const float4*)(g_xw + (size_t)c * 16 + q * 4);
        acc.x += w * v.x; acc.y += w * v.y; acc.z += w * v.z; acc.w += w * v.w;
    }
    if (valid)
        *(float4*)(e5 + (size_t)row * 16 + q * 4) = acc;

    float m = fmaxf(fmaxf(acc.x, acc.y), fmaxf(acc.z, acc.w));
    m = fmaxf(m, __shfl_xor_sync(0xffffffffu, m, 1));
    m = fmaxf(m, __shfl_xor_sync(0xffffffffu, m, 2));
    float s = expf(acc.x - m) + expf(acc.y - m) + expf(acc.z - m) + expf(acc.w - m);
    s += __shfl_xor_sync(0xffffffffu, s, 1);
    s += __shfl_xor_sync(0xffffffffu, s, 2);
    float lse = m + logf(s);
    if (valid) {
        float4 o;
        o.x = acc.x - lse; o.y = acc.y - lse; o.z = acc.z - lse; o.w = acc.w - lse;
        *(float4*)(out + (size_t)row * 16 + q * 4) = o;
    }
}

// ----------------------------------------------------------------------------
// Launch
// ----------------------------------------------------------------------------
extern "C" void kernel_launch(void* const* d_in, const int* in_sizes, int n_in,
                              void* d_out, int out_size) {
    const float* x    = (const float*)d_in[0];
    const int*   erow = (const int*)d_in[1];
    const int*   ecol = (const int*)d_in[2];
    const float* ew   = (const float*)d_in[3];
    const float* W1 = (const float*)d_in[4];  const float* b1 = (const float*)d_in[5];
    const float* W2 = (const float*)d_in[6];  const float* b2 = (const float*)d_in[7];
    const float* W3 = (const float*)d_in[8];  const float* b3 = (const float*)d_in[9];
    const float* W4 = (const float*)d_in[10]; const float* b4 = (const float*)d_in[11];
    const float* W5 = (const float*)d_in[12]; const float* b5 = (const float*)d_in[13];

    float* out = (float*)d_out;
    float* e1 = out + (size_t)N_NODES * 16;
    float* e2 = e1 + (size_t)N_NODES * 64;
    float* e3 = e2 + (size_t)N_NODES * 64;
    float* e4 = e3 + (size_t)N_NODES * 64;
    float* e5 = e4 + (size_t)N_NODES * 64;

    // Host-side attribute set (idempotent, not an allocation).
    cudaFuncSetAttribute(gemm_tc64_kernel<128, false>,
                         cudaFuncAttributeMaxDynamicSharedMemorySize, SMEM_TC64);
    cudaFuncSetAttribute(gemm_tc64_kernel<64, true>,
                         cudaFuncAttributeMaxDynamicSharedMemorySize, SMEM_TC64);

    const int GB128 = (N_NODES + 127) / 128;   // 391 tc gemm blocks
    const int GB64  = (N_NODES + 63) / 64;     // 782 scalar gemm blocks
    const int NB_N  = (N_NODES + 255) / 256;
    const int NB_E  = (N_EDGES + 255) / 256;
    const int AGG64 = (N_NODES * 16 + 255) / 256;
    const int AGG16 = (N_NODES * 4 + 255) / 256;

    // Layer-1 GEMM (tc), then CSR build.
    gemm_tc64_kernel<128, false><<<GB128, 512, SMEM_TC64>>>(x, W1);
    zero_deg_kernel<<<NB_N, 256>>>();
    hist_kernel<<<NB_E, 256>>>(erow);
    scan1_kernel<<<NB, 256>>>();
    scan2_kernel<<<1, 64>>>();
    scan3_kernel<<<NB_N, 256>>>();
    fill_kernel<<<NB_E, 256>>>(erow, ecol, ew);

    // Layer 1 aggregation
    agg64_kernel<<<AGG64, 256>>>(b1, e1);

    // Layer 2
    gemm_tc64_kernel<64, true><<<GB128, 512, SMEM_TC64>>>(e1, W2);
    agg64_kernel<<<AGG64, 256>>>(b2, e2);

    // Layer 3
    gemm_tc64_kernel<64, true><<<GB128, 512, SMEM_TC64>>>(e2, W3);
    agg64_kernel<<<AGG64, 256>>>(b3, e3);

    // Layer 4
    gemm_tc64_kernel<64, true><<<GB128, 512, SMEM_TC64>>>(e3, W4);
    agg64_kernel<<<AGG64, 256>>>(b4, e4);

    // Layer 5: 64 -> 16 (scalar GEMM), then agg + fused log_softmax
    gemm_kernel<64, 16, true><<<GB64, 64>>>(e4, W5);
    agg16_lsm_kernel<<<AGG16, 256>>>(b5, e5, out);
}

// round 15
// speedup vs baseline: 1.4076x; 1.4076x over previous
#include <cuda_runtime.h>

// ----------------------------------------------------------------------------
// GCN 5-layer inference, N=50000 nodes, E=800000 edges, 128->64->64->64->64->16
//
// Output layout (flattened tuple): [log_softmax N*16][e1 N*64][e2][e3][e4][e5 N*16]
//
// This round (vs 204.8us R7 best):
//   - Tensor-core branch abandoned (258/270us: staging-bound, 1 block/SM).
//   - CSR build chain runs on a side stream CONCURRENT with the layer-1 GEMM
//     (event fork/join; both branches join before agg1). ~20us hidden.
//   - agg16 + log_softmax fused (proven in R12/R14).
//   - All kernels otherwise byte-identical to the proven 204.8us R7 code.
// ----------------------------------------------------------------------------

constexpr int N_NODES = 50000;
constexpr int N_EDGES = 800000;
constexpr int SCAN_CHUNK = 1024;                              // elements per scan block
constexpr int NB = (N_NODES + SCAN_CHUNK - 1) / SCAN_CHUNK;   // 49 scan blocks

// Scratch for the per-layer dense GEMM result (max N x 64 fp32 = 12.8 MB).
__device__ float g_xw[(size_t)N_NODES * 64];

// CSR scratch
__device__ int   g_deg[N_NODES];        // histogram, then reused as fill cursor
__device__ int   g_off[N_NODES + 1];    // exclusive prefix offsets
__device__ int   g_bsum[NB];            // scan block partials
__device__ int   g_ecol[N_EDGES];       // row-sorted cols
__device__ float g_ew[N_EDGES];         // row-sorted weights

// ----------------------------------------------------------------------------
// Dense GEMM: g_xw[N x COLS] = act(X)[N x K] @ W[K x COLS]
// 64-row tile per block; thread tile = 4 rows x 4 cols; K chunked by 64.
// (Proven R7 kernel: 19.0us @ K=64,COLS=64.)
// ----------------------------------------------------------------------------
template <int K, int COLS, bool RELU>
__global__ void gemm_kernel(const float* __restrict__ X, const float* __restrict__ W) {
    constexpr int TX = COLS / 4;
    constexpr int NT = TX * 16;

    __shared__ float sx[64][68];     // +4 floats: 16B-aligned skew, conflict-free
    __shared__ float sw[64][COLS];

    const int tid  = threadIdx.x;
    const int tx   = tid % TX;
    const int ty   = tid / TX;
    const int row0 = blockIdx.x * 64;

    float4 acc[4];
#pragma unroll
    for (int r = 0; r < 4; r++) acc[r] = make_float4(0.f, 0.f, 0.f, 0.f);

    for (int kt = 0; kt < K; kt += 64) {
        if (kt) __syncthreads();

        for (int i = tid; i < 64 * 16; i += NT) {
            int r = i >> 4, q = i & 15;
            int gr = row0 + r;
            float4 v = make_float4(0.f, 0.f, 0.f, 0.f);
            if (gr < N_NODES)
                v = *(const float4*)(X + (size_t)gr * K + kt + q * 4);
            if (RELU) {
                v.x = fmaxf(v.x, 0.f); v.y = fmaxf(v.y, 0.f);
                v.z = fmaxf(v.z, 0.f); v.w = fmaxf(v.w, 0.f);
            }
            *(float4*)&sx[r][q * 4] = v;
        }
        for (int i = tid; i < 64 * (COLS / 4); i += NT) {
            int k = i / (COLS / 4), q = i % (COLS / 4);
            *(float4*)&sw[k][q * 4] = *(const float4*)(W + (size_t)(kt + k) * COLS + q * 4);
        }
        __syncthreads();

#pragma unroll
        for (int k = 0; k < 64; k += 4) {
            float4 b0 = *(const float4*)&sw[k + 0][tx * 4];
            float4 b1 = *(const float4*)&sw[k + 1][tx * 4];
            float4 b2 = *(const float4*)&sw[k + 2][tx * 4];
            float4 b3 = *(const float4*)&sw[k + 3][tx * 4];
#pragma unroll
            for (int r = 0; r < 4; r++) {
                float4 a = *(const float4*)&sx[ty * 4 + r][k];
                acc[r].x += a.x * b0.x; acc[r].y += a.x * b0.y;
                acc[r].z += a.x * b0.z; acc[r].w += a.x * b0.w;
                acc[r].x += a.y * b1.x; acc[r].y += a.y * b1.y;
                acc[r].z += a.y * b1.z; acc[r].w += a.y * b1.w;
                acc[r].x += a.z * b2.x; acc[r].y += a.z * b2.y;
                acc[r].z += a.z * b2.z; acc[r].w += a.z * b2.w;
                acc[r].x += a.w * b3.x; acc[r].y += a.w * b3.y;
                acc[r].z += a.w * b3.z; acc[r].w += a.w * b3.w;
            }
        }
    }

#pragma unroll
    for (int r = 0; r < 4; r++) {
        int gr = row0 + ty * 4 + r;
        if (gr < N_NODES)
            *(float4*)(g_xw + (size_t)gr * COLS + tx * 4) = acc[r];
    }
}

// ----------------------------------------------------------------------------
// CSR build (proven R7 version)
// ----------------------------------------------------------------------------
__global__ void zero_deg_kernel() {
    int i = blockIdx.x * blockDim.x + threadIdx.x;
    if (i < N_NODES) g_deg[i] = 0;
}

__global__ void hist_kernel(const int* __restrict__ erow) {
    int e = blockIdx.x * blockDim.x + threadIdx.x;
    if (e < N_EDGES) atomicAdd(&g_deg[__ldg(erow + e)], 1);
}

__global__ void scan1_kernel() {
    __shared__ int sh[256];
    int b = blockIdx.x, t = threadIdx.x;
    int base = b * SCAN_CHUNK + t * 4;
    int d0 = 0, d1 = 0, d2 = 0, d3 = 0;
    if (base + 0 < N_NODES) d0 = g_deg[base + 0];
    if (base + 1 < N_NODES) d1 = g_deg[base + 1];
    if (base + 2 < N_NODES) d2 = g_deg[base + 2];
    if (base + 3 < N_NODES) d3 = g_deg[base + 3];
    int s = d0 + d1 + d2 + d3;
    sh[t] = s;
    __syncthreads();
    for (int off = 1; off < 256; off <<= 1) {
        int v = (t >= off) ? sh[t - off] : 0;
        __syncthreads();
        sh[t] += v;
        __syncthreads();
    }
    int excl = sh[t] - s;
    if (t == 255) g_bsum[b] = sh[255];
    if (base + 0 < N_NODES) g_off[base + 0] = excl;
    if (base + 1 < N_NODES) g_off[base + 1] = excl + d0;
    if (base + 2 < N_NODES) g_off[base + 2] = excl + d0 + d1;
    if (base + 3 < N_NODES) g_off[base + 3] = excl + d0 + d1 + d2;
}

__global__ void scan2_kernel() {
    __shared__ int sh[64];
    int t = threadIdx.x;
    int v = (t < NB) ? g_bsum[t] : 0;
    sh[t] = v;
    __syncthreads();
    for (int off = 1; off < 64; off <<= 1) {
        int u = (t >= off) ? sh[t - off] : 0;
        __syncthreads();
        sh[t] += u;
        __syncthreads();
    }
    if (t < NB) g_bsum[t] = sh[t] - v;   // exclusive
}

__global__ void scan3_kernel() {
    int i = blockIdx.x * blockDim.x + threadIdx.x;
    if (i < N_NODES) {
        g_off[i] += g_bsum[i / SCAN_CHUNK];
        g_deg[i] = 0;                    // fill cursor
    }
    if (i == 0) g_off[N_NODES] = N_EDGES;
}

__global__ void fill_kernel(const int* __restrict__ erow, const int* __restrict__ ecol,
                            const float* __restrict__ ew) {
    int e = blockIdx.x * blockDim.x + threadIdx.x;
    if (e >= N_EDGES) return;
    int r = __ldg(erow + e);
    int pos = g_off[r] + atomicAdd(&g_deg[r], 1);
    g_ecol[pos] = __ldg(ecol + e);
    g_ew[pos]   = __ldg(ew + e);
}

// ----------------------------------------------------------------------------
// Per-row aggregation (64 features): dst[row] = b + sum w_e * g_xw[col_e]
// ----------------------------------------------------------------------------
__global__ void agg64_kernel(const float* __restrict__ bias, float* __restrict__ dst) {
    int t = blockIdx.x * blockDim.x + threadIdx.x;
    if (t >= N_NODES * 16) return;
    int row = t >> 4, q = t & 15;
    float4 acc = *(const float4*)(bias + q * 4);
    int i = __ldg(&g_off[row]), end = __ldg(&g_off[row + 1]);
    for (; i + 1 < end; i += 2) {
        int c0 = __ldg(&g_ecol[i]);     float w0 = __ldg(&g_ew[i]);
        int c1 = __ldg(&g_ecol[i + 1]); float w1 = __ldg(&g_ew[i + 1]);
        float4 v0 = *(const float4*)(g_xw + (size_t)c0 * 64 + q * 4);
        float4 v1 = *(const float4*)(g_xw + (size_t)c1 * 64 + q * 4);
        acc.x += w0 * v0.x + w1 * v1.x;
        acc.y += w0 * v0.y + w1 * v1.y;
        acc.z += w0 * v0.z + w1 * v1.z;
        acc.w += w0 * v0.w + w1 * v1.w;
    }
    if (i < end) {
        int c = __ldg(&g_ecol[i]); float w = __ldg(&g_ew[i]);
        float4 v = *(const float4*)(g_xw + (size_t)c * 64 + q * 4);
        acc.x += w * v.x; acc.y += w * v.y; acc.z += w * v.z; acc.w += w * v.w;
    }
    *(float4*)(dst + (size_t)row * 64 + q * 4) = acc;
}

// ----------------------------------------------------------------------------
// Layer-5 aggregation (16 features) with FUSED log_softmax (proven R12/R14).
// Quad of threads (q=0..3) owns a row; reduction via shfl_xor 1,2.
// ----------------------------------------------------------------------------
__global__ void agg16_lsm_kernel(const float* __restrict__ bias,
                                 float* __restrict__ e5, float* __restrict__ out) {
    int t = blockIdx.x * blockDim.x + threadIdx.x;
    bool valid = (t < N_NODES * 4);
    int tc = valid ? t : (N_NODES * 4 - 1);
    int row = tc >> 2, q = tc & 3;

    float4 acc = *(const float4*)(bias + q * 4);
    int i = __ldg(&g_off[row]), end = __ldg(&g_off[row + 1]);
    for (; i + 1 < end; i += 2) {
        int c0 = __ldg(&g_ecol[i]);     float w0 = __ldg(&g_ew[i]);
        int c1 = __ldg(&g_ecol[i + 1]); float w1 = __ldg(&g_ew[i + 1]);
        float4 v0 = *(const float4*)(g_xw + (size_t)c0 * 16 + q * 4);
        float4 v1 = *(const float4*)(g_xw + (size_t)c1 * 16 + q * 4);
        acc.x += w0 * v0.x + w1 * v1.x;
        acc.y += w0 * v0.y + w1 * v1.y;
        acc.z += w0 * v0.z + w1 * v1.z;
        acc.w += w0 * v0.w + w1 * v1.w;
    }
    if (i < end) {
        int c = __ldg(&g_ecol[i]); float w = __ldg(&g_ew[i]);
        float4 v = *(const float4*)(g_xw + (size_t)c * 16 + q * 4);
        acc.x += w * v.x; acc.y += w * v.y; acc.z += w * v.z; acc.w += w * v.w;
    }
    if (valid)
        *(float4*)(e5 + (size_t)row * 16 + q * 4) = acc;

    float m = fmaxf(fmaxf(acc.x, acc.y), fmaxf(acc.z, acc.w));
    m = fmaxf(m, __shfl_xor_sync(0xffffffffu, m, 1));
    m = fmaxf(m, __shfl_xor_sync(0xffffffffu, m, 2));
    float s = expf(acc.x - m) + expf(acc.y - m) + expf(acc.z - m) + expf(acc.w - m);
    s += __shfl_xor_sync(0xffffffffu, s, 1);
    s += __shfl_xor_sync(0xffffffffu, s, 2);
    float lse = m + logf(s);
    if (valid) {
        float4 o;
        o.x = acc.x - lse; o.y = acc.y - lse; o.z = acc.z - lse; o.w = acc.w - lse;
        *(float4*)(out + (size_t)row * 16 + q * 4) = o;
    }
}

// ----------------------------------------------------------------------------
// Launch: CSR build forked onto a side stream, concurrent with layer-1 GEMM.
// Event fork/join is the documented multi-stream graph-capture pattern; the
// side stream/events are created once (handles only — no device memory, and
// the enqueued work is identical on every call).
// ----------------------------------------------------------------------------
extern "C" void kernel_launch(void* const* d_in, const int* in_sizes, int n_in,
                              void* d_out, int out_size) {
    const float* x    = (const float*)d_in[0];
    const int*   erow = (const int*)d_in[1];
    const int*   ecol = (const int*)d_in[2];
    const float* ew   = (const float*)d_in[3];
    const float* W1 = (const float*)d_in[4];  const float* b1 = (const float*)d_in[5];
    const float* W2 = (const float*)d_in[6];  const float* b2 = (const float*)d_in[7];
    const float* W3 = (const float*)d_in[8];  const float* b3 = (const float*)d_in[9];
    const float* W4 = (const float*)d_in[10]; const float* b4 = (const float*)d_in[11];
    const float* W5 = (const float*)d_in[12]; const float* b5 = (const float*)d_in[13];

    float* out = (float*)d_out;
    float* e1 = out + (size_t)N_NODES * 16;
    float* e2 = e1 + (size_t)N_NODES * 64;
    float* e3 = e2 + (size_t)N_NODES * 64;
    float* e4 = e3 + (size_t)N_NODES * 64;
    float* e5 = e4 + (size_t)N_NODES * 64;

    static cudaStream_t s_side = nullptr;
    static cudaEvent_t  evFork = nullptr, evJoin = nullptr;
    if (s_side == nullptr) {
        cudaStreamCreateWithFlags(&s_side, cudaStreamNonBlocking);
        cudaEventCreateWithFlags(&evFork, cudaEventDisableTiming);
        cudaEventCreateWithFlags(&evJoin, cudaEventDisableTiming);
    }

    const int GB    = (N_NODES + 63) / 64;
    const int NB_N  = (N_NODES + 255) / 256;
    const int NB_E  = (N_EDGES + 255) / 256;
    const int AGG64 = (N_NODES * 16 + 255) / 256;
    const int AGG16 = (N_NODES * 4 + 255) / 256;

    // ---- fork: CSR build on side stream, layer-1 GEMM on main stream ----
    cudaEventRecord(evFork, 0);
    cudaStreamWaitEvent(s_side, evFork, 0);

    zero_deg_kernel<<<NB_N, 256, 0, s_side>>>();
    hist_kernel<<<NB_E, 256, 0, s_side>>>(erow);
    scan1_kernel<<<NB, 256, 0, s_side>>>();
    scan2_kernel<<<1, 64, 0, s_side>>>();
    scan3_kernel<<<NB_N, 256, 0, s_side>>>();
    fill_kernel<<<NB_E, 256, 0, s_side>>>(erow, ecol, ew);
    cudaEventRecord(evJoin, s_side);

    gemm_kernel<128, 64, false><<<GB, 256>>>(x, W1);

    // ---- join: both g_xw and the CSR are needed by agg1 ----
    cudaStreamWaitEvent(0, evJoin, 0);

    // Layer 1 aggregation
    agg64_kernel<<<AGG64, 256>>>(b1, e1);

    // Layer 2
    gemm_kernel<64, 64, true><<<GB, 256>>>(e1, W2);
    agg64_kernel<<<AGG64, 256>>>(b2, e2);

    // Layer 3
    gemm_kernel<64, 64, true><<<GB, 256>>>(e2, W3);
    agg64_kernel<<<AGG64, 256>>>(b3, e3);

    // Layer 4
    gemm_kernel<64, 64, true><<<GB, 256>>>(e3, W4);
    agg64_kernel<<<AGG64, 256>>>(b4, e4);

    // Layer 5: 64 -> 16, then agg + fused log_softmax
    gemm_kernel<64, 16, true><<<GB, 64>>>(e4, W5);
    agg16_lsm_kernel<<<AGG16, 256>>>(b5, e5, out);
}